// round 7
// baseline (speedup 1.0000x reference)
#include <cuda_runtime.h>
#include <cstdint>

#define N_NODES 8192
#define FEAT    256

// ---------------------------------------------------------------------------
// Device scratch
// ---------------------------------------------------------------------------
__device__ __align__(128) float g_d[N_NODES];            // rsqrt degree
__device__ __align__(128) float g_supp[N_NODES * FEAT];  // raw fp32 (input @ weight)

// ---------------------------------------------------------------------------
// helpers
// ---------------------------------------------------------------------------
__device__ __forceinline__ uint32_t smem_to_u32(const void* p) {
    uint32_t a;
    asm("{ .reg .u64 t; cvta.to.shared.u64 t, %1; cvt.u32.u64 %0, t; }" : "=r"(a) : "l"(p));
    return a;
}
#define CP_ASYNC_CG(smem, gptr) \
    asm volatile("cp.async.cg.shared.global [%0], [%1], 16;" :: "r"((uint32_t)(smem)), "l"(gptr) : "memory")
#define CP_COMMIT() asm volatile("cp.async.commit_group;" ::: "memory")
#define CP_WAIT2()  asm volatile("cp.async.wait_group 2;" ::: "memory")

__device__ __forceinline__ void mma_tf32(float* c, const uint32_t* a, const uint32_t* b) {
    asm volatile(
        "mma.sync.aligned.m16n8k8.row.col.f32.tf32.tf32.f32 "
        "{%0,%1,%2,%3}, {%4,%5,%6,%7}, {%8,%9}, {%0,%1,%2,%3};"
        : "+f"(c[0]), "+f"(c[1]), "+f"(c[2]), "+f"(c[3])
        : "r"(a[0]), "r"(a[1]), "r"(a[2]), "r"(a[3]), "r"(b[0]), "r"(b[1]));
}

// ---------------------------------------------------------------------------
// Fused kernel 1:
//   blocks [0, 128)      : supp0 = input @ weight   (raw fp32, no d)
//   blocks [128, 8320)   : d[row] = rsqrt(1 + rowsum(adj))
// Occupancy 3 CTAs/SM; rowsum fully unrolled (8 independent LDG.128/thread)
// so DRAM saturates even at reduced occupancy while GEMM blocks overlap.
// ---------------------------------------------------------------------------
#define BM 128
#define BN 128
#define BK 16
#define TM 8
#define TN 8
#define GEMM_BLOCKS ((N_NODES / BM) * (FEAT / BN))   // 128

__global__ __launch_bounds__(256, 3)
void prep_fused_kernel(const float* __restrict__ adj,
                       const float* __restrict__ input,
                       const float* __restrict__ weight) {
    __shared__ float sh[2 * BK * 128];    // 16KB: As | Bs
    const int tid = threadIdx.x;

    if (blockIdx.x >= GEMM_BLOCKS) {
        // ---- rowsum path: 8 independent vector loads, max MLP ----
        const int row = blockIdx.x - GEMM_BLOCKS;
        const float4* rp = reinterpret_cast<const float4*>(adj + (size_t)row * N_NODES);
        float4 v[8];
        #pragma unroll
        for (int i = 0; i < 8; i++) v[i] = __ldg(rp + tid + i * 256);
        float s0 = 0.f, s1 = 0.f, s2 = 0.f, s3 = 0.f;
        #pragma unroll
        for (int i = 0; i < 8; i += 4) {
            s0 += v[i].x + v[i].y + v[i].z + v[i].w;
            s1 += v[i + 1].x + v[i + 1].y + v[i + 1].z + v[i + 1].w;
            s2 += v[i + 2].x + v[i + 2].y + v[i + 2].z + v[i + 2].w;
            s3 += v[i + 3].x + v[i + 3].y + v[i + 3].z + v[i + 3].w;
        }
        float s = (s0 + s1) + (s2 + s3);
        #pragma unroll
        for (int o = 16; o > 0; o >>= 1) s += __shfl_down_sync(0xffffffffu, s, o);
        const int lane = tid & 31;
        const int w = tid >> 5;
        if (lane == 0) sh[w] = s;
        __syncthreads();
        if (w == 0) {
            s = (lane < 8) ? sh[lane] : 0.0f;
            #pragma unroll
            for (int o = 4; o > 0; o >>= 1) s += __shfl_down_sync(0xffffffffu, s, o);
            if (lane == 0) g_d[row] = rsqrtf(s + 1.0f);
        }
        return;
    }

    // ---- small GEMM path: supp0 = input @ weight ----
    float (*As)[BM] = reinterpret_cast<float (*)[BM]>(sh);
    float (*Bs)[BN] = reinterpret_cast<float (*)[BN]>(sh + BK * BM);
    const int rowBase = (blockIdx.x >> 1) * BM;
    const int colBase = (blockIdx.x & 1) * BN;
    const int ty = tid >> 4, tx = tid & 15;
    const int aRow = tid >> 2, aCol = (tid & 3) << 2;
    const int bRow = tid >> 5, bCol = (tid & 31) << 2;
    const int K = FEAT;

    float acc[TM][TN];
    #pragma unroll
    for (int m = 0; m < TM; m++)
        #pragma unroll
        for (int n = 0; n < TN; n++) acc[m][n] = 0.0f;

    for (int k0 = 0; k0 < K; k0 += BK) {
        #pragma unroll
        for (int r = 0; r < BM; r += 64) {
            float4 v = *reinterpret_cast<const float4*>(input + (size_t)(rowBase + aRow + r) * K + (k0 + aCol));
            As[aCol + 0][aRow + r] = v.x; As[aCol + 1][aRow + r] = v.y;
            As[aCol + 2][aRow + r] = v.z; As[aCol + 3][aRow + r] = v.w;
        }
        #pragma unroll
        for (int r = 0; r < BK; r += 8)
            *reinterpret_cast<float4*>(&Bs[bRow + r][bCol]) =
                *reinterpret_cast<const float4*>(weight + (size_t)(k0 + bRow + r) * FEAT + (colBase + bCol));
        __syncthreads();
        #pragma unroll
        for (int k = 0; k < BK; k++) {
            float a[TM], b[TN];
            *reinterpret_cast<float4*>(&a[0]) = *reinterpret_cast<const float4*>(&As[k][ty * TM]);
            *reinterpret_cast<float4*>(&a[4]) = *reinterpret_cast<const float4*>(&As[k][ty * TM + 4]);
            *reinterpret_cast<float4*>(&b[0]) = *reinterpret_cast<const float4*>(&Bs[k][tx * TN]);
            *reinterpret_cast<float4*>(&b[4]) = *reinterpret_cast<const float4*>(&Bs[k][tx * TN + 4]);
            #pragma unroll
            for (int m = 0; m < TM; m++)
                #pragma unroll
                for (int n = 0; n < TN; n++) acc[m][n] = fmaf(a[m], b[n], acc[m][n]);
        }
        __syncthreads();
    }
    #pragma unroll
    for (int m = 0; m < TM; m++) {
        const int gr = rowBase + ty * TM + m;
        #pragma unroll
        for (int n4 = 0; n4 < TN; n4 += 4) {
            const int gc = colBase + tx * TN + n4;
            float4 o;
            o.x = acc[m][n4 + 0]; o.y = acc[m][n4 + 1];
            o.z = acc[m][n4 + 2]; o.w = acc[m][n4 + 3];
            *reinterpret_cast<float4*>(g_supp + (size_t)gr * FEAT + gc) = o;
        }
    }
}

// ---------------------------------------------------------------------------
// Kernel 2: out = d_i * (adj @ (d_k*supp0)) + d_i^2 * supp0[i,:] + bias
// TF32 mma.sync m16n8k8, CTA 128x128, 16 warps (warp tile 32x32),
// K-step 32, 4-stage cp.async pipeline, raw-bit tf32 operands.
// ---------------------------------------------------------------------------
#define SA 36                                  // A smem row stride (floats)
#define SB 136                                 // B smem row stride (floats)
#define D_OFF (128 * SA + 32 * SB)             // 8960
#define STAGE_FLOATS (D_OFF + 32)              // 8992
#define STAGE_BYTES  (STAGE_FLOATS * 4)        // 35968
#define NSTAGES 4
#define MAIN_SMEM (NSTAGES * STAGE_BYTES)      // 143872
#define NITER (N_NODES / 32)                   // 256

__global__ __launch_bounds__(512, 1)
void gcn_main_gemm(const float* __restrict__ adj,
                   float* __restrict__ out,
                   const float* __restrict__ bias) {
    extern __shared__ float smem[];
    const uint32_t sb_u32 = smem_to_u32(smem);

    const int tid = threadIdx.x;
    const int wid = tid >> 5;
    const int lane = tid & 31;
    const int gid = lane >> 2;      // 0..7
    const int tig = lane & 3;       // 0..3
    const int wm = wid >> 2;        // 0..3  (32-row band)
    const int wn = wid & 3;         // 0..3  (32-col band)

    const int mBase = blockIdx.y * 128;
    const int nBase = blockIdx.x * 128;

    const float* Abase = adj + (size_t)mBase * N_NODES;
    const float* Bbase = g_supp + nBase;

    float acc[2][4][4];
    #pragma unroll
    for (int mt = 0; mt < 2; mt++)
        #pragma unroll
        for (int nt = 0; nt < 4; nt++)
            #pragma unroll
            for (int c = 0; c < 4; c++) acc[mt][nt][c] = 0.0f;

    auto load_stage = [&](int s) {
        const int slot = s & (NSTAGES - 1);
        const uint32_t a_s = sb_u32 + slot * STAGE_BYTES;
        const uint32_t b_s = a_s + 128 * SA * 4;
        const uint32_t d_s = a_s + D_OFF * 4;
        const float* ag = Abase + s * 32;
        const float* bg = Bbase + (size_t)(s * 32) * FEAT;
        #pragma unroll
        for (int i = 0; i < 2; i++) {            // A: 1024 16B granules
            const int g = tid + i * 512;
            const int r = g >> 3, q = g & 7;
            CP_ASYNC_CG(a_s + (r * SA + q * 4) * 4, ag + (size_t)r * N_NODES + q * 4);
        }
        #pragma unroll
        for (int i = 0; i < 2; i++) {            // B: 1024 16B granules
            const int g = tid + i * 512;
            const int k = g >> 5, q = g & 31;
            CP_ASYNC_CG(b_s + (k * SB + q * 4) * 4, bg + (size_t)k * FEAT + q * 4);
        }
        if (tid < 8) {                           // D: 32 floats
            CP_ASYNC_CG(d_s + tid * 16, g_d + s * 32 + tid * 4);
        }
    };

    #pragma unroll
    for (int p = 0; p < 3; p++) { load_stage(p); CP_COMMIT(); }

    for (int s = 0; s < NITER; s++) {
        CP_WAIT2();
        __syncthreads();

        if (s + 3 < NITER) { load_stage(s + 3); }
        CP_COMMIT();

        const int slot = s & (NSTAGES - 1);
        const float* As = smem + slot * STAGE_FLOATS;
        const float* Bs = As + 128 * SA;
        const float* Ds = As + D_OFF;

        #pragma unroll
        for (int k8 = 0; k8 < 4; k8++) {
            const int kk = k8 * 8;
            const float d0 = Ds[kk + tig];
            const float d1 = Ds[kk + tig + 4];
            uint32_t a[2][4], b[4][2];
            #pragma unroll
            for (int mt = 0; mt < 2; mt++) {
                const int r = wm * 32 + mt * 16 + gid;
                a[mt][0] = __float_as_uint(As[r * SA + kk + tig]);
                a[mt][1] = __float_as_uint(As[(r + 8) * SA + kk + tig]);
                a[mt][2] = __float_as_uint(As[r * SA + kk + tig + 4]);
                a[mt][3] = __float_as_uint(As[(r + 8) * SA + kk + tig + 4]);
            }
            #pragma unroll
            for (int nt = 0; nt < 4; nt++) {
                const int n = wn * 32 + nt * 8 + gid;
                b[nt][0] = __float_as_uint(Bs[(kk + tig) * SB + n] * d0);
                b[nt][1] = __float_as_uint(Bs[(kk + tig + 4) * SB + n] * d1);
            }
            #pragma unroll
            for (int mt = 0; mt < 2; mt++)
                #pragma unroll
                for (int nt = 0; nt < 4; nt++)
                    mma_tf32(acc[mt][nt], a[mt], b[nt]);
        }
        __syncthreads();
    }

    // epilogue: out = d_i * acc + d_i^2 * supp0[i,:] + bias
    #pragma unroll
    for (int mt = 0; mt < 2; mt++) {
        const int r0 = mBase + wm * 32 + mt * 16 + gid;
        const int r1 = r0 + 8;
        const float d0 = g_d[r0];
        const float d1 = g_d[r1];
        #pragma unroll
        for (int nt = 0; nt < 4; nt++) {
            const int col = nBase + wn * 32 + nt * 8 + tig * 2;
            const float2 bv = *reinterpret_cast<const float2*>(bias + col);
            const float2 s0 = *reinterpret_cast<const float2*>(g_supp + (size_t)r0 * FEAT + col);
            const float2 s1 = *reinterpret_cast<const float2*>(g_supp + (size_t)r1 * FEAT + col);
            float2 o0, o1;
            o0.x = fmaf(d0, acc[mt][nt][0] + d0 * s0.x, bv.x);
            o0.y = fmaf(d0, acc[mt][nt][1] + d0 * s0.y, bv.y);
            o1.x = fmaf(d1, acc[mt][nt][2] + d1 * s1.x, bv.x);
            o1.y = fmaf(d1, acc[mt][nt][3] + d1 * s1.y, bv.y);
            *reinterpret_cast<float2*>(out + (size_t)r0 * FEAT + col) = o0;
            *reinterpret_cast<float2*>(out + (size_t)r1 * FEAT + col) = o1;
        }
    }
}

// ---------------------------------------------------------------------------
extern "C" void kernel_launch(void* const* d_in, const int* in_sizes, int n_in,
                              void* d_out, int out_size) {
    const float* input  = (const float*)d_in[0];   // [8192, 256]
    const float* adj    = (const float*)d_in[1];   // [8192, 8192]
    const float* weight = (const float*)d_in[2];   // [256, 256]
    const float* bias   = (const float*)d_in[3];   // [256]
    float* out = (float*)d_out;

    cudaFuncSetAttribute(gcn_main_gemm, cudaFuncAttributeMaxDynamicSharedMemorySize, MAIN_SMEM);

    prep_fused_kernel<<<GEMM_BLOCKS + N_NODES, 256>>>(adj, input, weight);
    {
        dim3 grid(FEAT / 128, N_NODES / 128);   // (2, 64)
        gcn_main_gemm<<<grid, 512, MAIN_SMEM>>>(adj, out, bias);
    }
}

// round 8
// speedup vs baseline: 1.2283x; 1.2283x over previous
#include <cuda_runtime.h>
#include <cstdint>

#define N_NODES 8192
#define FEAT    256

// ---------------------------------------------------------------------------
// Device scratch
// ---------------------------------------------------------------------------
__device__ __align__(128) float g_d[N_NODES];            // rsqrt degree
__device__ __align__(128) float g_supp[N_NODES * FEAT];  // raw fp32 (input @ weight)

// ---------------------------------------------------------------------------
// helpers
// ---------------------------------------------------------------------------
__device__ __forceinline__ uint32_t smem_to_u32(const void* p) {
    uint32_t a;
    asm("{ .reg .u64 t; cvta.to.shared.u64 t, %1; cvt.u32.u64 %0, t; }" : "=r"(a) : "l"(p));
    return a;
}
#define CP_ASYNC_CG(smem, gptr) \
    asm volatile("cp.async.cg.shared.global [%0], [%1], 16;" :: "r"((uint32_t)(smem)), "l"(gptr) : "memory")
#define CP_COMMIT() asm volatile("cp.async.commit_group;" ::: "memory")
#define CP_WAIT3()  asm volatile("cp.async.wait_group 3;" ::: "memory")

__device__ __forceinline__ void mma_tf32(float* c, const uint32_t* a, const uint32_t* b) {
    asm volatile(
        "mma.sync.aligned.m16n8k8.row.col.f32.tf32.tf32.f32 "
        "{%0,%1,%2,%3}, {%4,%5,%6,%7}, {%8,%9}, {%0,%1,%2,%3};"
        : "+f"(c[0]), "+f"(c[1]), "+f"(c[2]), "+f"(c[3])
        : "r"(a[0]), "r"(a[1]), "r"(a[2]), "r"(a[3]), "r"(b[0]), "r"(b[1]));
}

// ---------------------------------------------------------------------------
// Fused kernel 1 (R6 version verbatim — measured 74us):
//   blocks [0, 128)      : supp0 = input @ weight
//   blocks [128, 8320)   : d[row] = rsqrt(1 + rowsum(adj))
// ---------------------------------------------------------------------------
#define BM 128
#define BN 128
#define BK 16
#define TM 8
#define TN 8
#define GEMM_BLOCKS ((N_NODES / BM) * (FEAT / BN))   // 128

__global__ __launch_bounds__(256, 2)
void prep_fused_kernel(const float* __restrict__ adj,
                       const float* __restrict__ input,
                       const float* __restrict__ weight) {
    __shared__ float sh[2 * BK * 128];    // 16KB: As | Bs
    const int tid = threadIdx.x;

    if (blockIdx.x >= GEMM_BLOCKS) {
        // ---- rowsum path ----
        const int row = blockIdx.x - GEMM_BLOCKS;
        const float4* rp = reinterpret_cast<const float4*>(adj + (size_t)row * N_NODES);
        float s = 0.0f;
        #pragma unroll 4
        for (int i = tid; i < N_NODES / 4; i += 256) {
            float4 v = __ldg(rp + i);
            s += (v.x + v.y) + (v.z + v.w);
        }
        #pragma unroll
        for (int o = 16; o > 0; o >>= 1) s += __shfl_down_sync(0xffffffffu, s, o);
        const int lane = tid & 31;
        const int w = tid >> 5;
        if (lane == 0) sh[w] = s;
        __syncthreads();
        if (w == 0) {
            s = (lane < 8) ? sh[lane] : 0.0f;
            #pragma unroll
            for (int o = 4; o > 0; o >>= 1) s += __shfl_down_sync(0xffffffffu, s, o);
            if (lane == 0) g_d[row] = rsqrtf(s + 1.0f);
        }
        return;
    }

    // ---- small GEMM path: supp0 = input @ weight ----
    float (*As)[BM] = reinterpret_cast<float (*)[BM]>(sh);
    float (*Bs)[BN] = reinterpret_cast<float (*)[BN]>(sh + BK * BM);
    const int rowBase = (blockIdx.x >> 1) * BM;
    const int colBase = (blockIdx.x & 1) * BN;
    const int ty = tid >> 4, tx = tid & 15;
    const int aRow = tid >> 2, aCol = (tid & 3) << 2;
    const int bRow = tid >> 5, bCol = (tid & 31) << 2;
    const int K = FEAT;

    float acc[TM][TN];
    #pragma unroll
    for (int m = 0; m < TM; m++)
        #pragma unroll
        for (int n = 0; n < TN; n++) acc[m][n] = 0.0f;

    for (int k0 = 0; k0 < K; k0 += BK) {
        #pragma unroll
        for (int r = 0; r < BM; r += 64) {
            float4 v = *reinterpret_cast<const float4*>(input + (size_t)(rowBase + aRow + r) * K + (k0 + aCol));
            As[aCol + 0][aRow + r] = v.x; As[aCol + 1][aRow + r] = v.y;
            As[aCol + 2][aRow + r] = v.z; As[aCol + 3][aRow + r] = v.w;
        }
        #pragma unroll
        for (int r = 0; r < BK; r += 8)
            *reinterpret_cast<float4*>(&Bs[bRow + r][bCol]) =
                *reinterpret_cast<const float4*>(weight + (size_t)(k0 + bRow + r) * FEAT + (colBase + bCol));
        __syncthreads();
        #pragma unroll
        for (int k = 0; k < BK; k++) {
            float a[TM], b[TN];
            *reinterpret_cast<float4*>(&a[0]) = *reinterpret_cast<const float4*>(&As[k][ty * TM]);
            *reinterpret_cast<float4*>(&a[4]) = *reinterpret_cast<const float4*>(&As[k][ty * TM + 4]);
            *reinterpret_cast<float4*>(&b[0]) = *reinterpret_cast<const float4*>(&Bs[k][tx * TN]);
            *reinterpret_cast<float4*>(&b[4]) = *reinterpret_cast<const float4*>(&Bs[k][tx * TN + 4]);
            #pragma unroll
            for (int m = 0; m < TM; m++)
                #pragma unroll
                for (int n = 0; n < TN; n++) acc[m][n] = fmaf(a[m], b[n], acc[m][n]);
        }
        __syncthreads();
    }
    #pragma unroll
    for (int m = 0; m < TM; m++) {
        const int gr = rowBase + ty * TM + m;
        #pragma unroll
        for (int n4 = 0; n4 < TN; n4 += 4) {
            const int gc = colBase + tx * TN + n4;
            float4 o;
            o.x = acc[m][n4 + 0]; o.y = acc[m][n4 + 1];
            o.z = acc[m][n4 + 2]; o.w = acc[m][n4 + 3];
            *reinterpret_cast<float4*>(g_supp + (size_t)gr * FEAT + gc) = o;
        }
    }
}

// ---------------------------------------------------------------------------
// Kernel 2: out = d_i * (adj @ (d_k*supp0)) + d_i^2 * supp0[i,:] + bias
// TF32 mma.sync m16n8k8, CTA 128x128, 8 warps (warp tile 64x32),
// K-step 32, 5-stage cp.async pipeline, single barrier per stage,
// register double-buffered fragments, raw-bit tf32 operands.
// ---------------------------------------------------------------------------
#define SA 36                                  // A smem row stride (floats)
#define SB 136                                 // B smem row stride (floats)
#define D_OFF (128 * SA + 32 * SB)             // 8960
#define STAGE_FLOATS (D_OFF + 32)              // 8992
#define STAGE_BYTES  (STAGE_FLOATS * 4)        // 35968
#define NSTAGES 5
#define PREF 4
#define MAIN_SMEM (NSTAGES * STAGE_BYTES)      // 179840
#define NITER (N_NODES / 32)                   // 256

__global__ __launch_bounds__(256, 1)
void gcn_main_gemm(const float* __restrict__ adj,
                   float* __restrict__ out,
                   const float* __restrict__ bias) {
    extern __shared__ float smem[];
    const uint32_t sb_u32 = smem_to_u32(smem);

    const int tid = threadIdx.x;
    const int wid = tid >> 5;
    const int lane = tid & 31;
    const int gid = lane >> 2;      // 0..7
    const int tig = lane & 3;       // 0..3
    const int wm = wid >> 2;        // 0..1  (64-row band)
    const int wn = wid & 3;         // 0..3  (32-col band)

    const int mBase = blockIdx.y * 128;
    const int nBase = blockIdx.x * 128;

    const float* Abase = adj + (size_t)mBase * N_NODES;
    const float* Bbase = g_supp + nBase;

    float acc[4][4][4];
    #pragma unroll
    for (int mt = 0; mt < 4; mt++)
        #pragma unroll
        for (int nt = 0; nt < 4; nt++)
            #pragma unroll
            for (int c = 0; c < 4; c++) acc[mt][nt][c] = 0.0f;

    auto load_stage = [&](int s) {
        const int slot = s % NSTAGES;
        const uint32_t a_s = sb_u32 + slot * STAGE_BYTES;
        const uint32_t b_s = a_s + 128 * SA * 4;
        const uint32_t d_s = a_s + D_OFF * 4;
        const float* ag = Abase + s * 32;
        const float* bg = Bbase + (size_t)(s * 32) * FEAT;
        #pragma unroll
        for (int i = 0; i < 4; i++) {            // A: 1024 16B granules
            const int g = tid + i * 256;
            const int r = g >> 3, q = g & 7;
            CP_ASYNC_CG(a_s + (r * SA + q * 4) * 4, ag + (size_t)r * N_NODES + q * 4);
        }
        #pragma unroll
        for (int i = 0; i < 4; i++) {            // B: 1024 16B granules
            const int g = tid + i * 256;
            const int k = g >> 5, q = g & 31;
            CP_ASYNC_CG(b_s + (k * SB + q * 4) * 4, bg + (size_t)k * FEAT + q * 4);
        }
        if (tid < 8) {                           // D: 32 floats
            CP_ASYNC_CG(d_s + tid * 16, g_d + s * 32 + tid * 4);
        }
    };

    #pragma unroll
    for (int p = 0; p < PREF; p++) { load_stage(p); CP_COMMIT(); }

    uint32_t af[2][4][4], bf[2][4][2];

    for (int s = 0; s < NITER; s++) {
        CP_WAIT3();          // group s landed (groups s+1..s+3 in flight)
        __syncthreads();     // all warps done computing stage s-1 -> slot reusable

        if (s + PREF < NITER) { load_stage(s + PREF); }
        CP_COMMIT();

        const int slot = s % NSTAGES;
        const float* As = smem + slot * STAGE_FLOATS;
        const float* Bs = As + 128 * SA;
        const float* Ds = As + D_OFF;

        // fragment loader for one k8 into register buffer `buf`
        auto ldfrag = [&](int k8, int buf) {
            const int kk = k8 * 8;
            const float d0 = Ds[kk + tig];
            const float d1 = Ds[kk + tig + 4];
            #pragma unroll
            for (int mt = 0; mt < 4; mt++) {
                const int r = wm * 64 + mt * 16 + gid;
                af[buf][mt][0] = __float_as_uint(As[r * SA + kk + tig]);
                af[buf][mt][1] = __float_as_uint(As[(r + 8) * SA + kk + tig]);
                af[buf][mt][2] = __float_as_uint(As[r * SA + kk + tig + 4]);
                af[buf][mt][3] = __float_as_uint(As[(r + 8) * SA + kk + tig + 4]);
            }
            #pragma unroll
            for (int nt = 0; nt < 4; nt++) {
                const int n = wn * 32 + nt * 8 + gid;
                bf[buf][nt][0] = __float_as_uint(Bs[(kk + tig) * SB + n] * d0);
                bf[buf][nt][1] = __float_as_uint(Bs[(kk + tig + 4) * SB + n] * d1);
            }
        };

        ldfrag(0, 0);
        #pragma unroll
        for (int k8 = 0; k8 < 4; k8++) {
            if (k8 < 3) ldfrag(k8 + 1, (k8 + 1) & 1);
            const int cur = k8 & 1;
            #pragma unroll
            for (int mt = 0; mt < 4; mt++)
                #pragma unroll
                for (int nt = 0; nt < 4; nt++)
                    mma_tf32(acc[mt][nt], af[cur][mt], bf[cur][nt]);
        }
    }

    // epilogue: out = d_i * acc + d_i^2 * supp0[i,:] + bias
    #pragma unroll
    for (int mt = 0; mt < 4; mt++) {
        const int r0 = mBase + wm * 64 + mt * 16 + gid;
        const int r1 = r0 + 8;
        const float d0 = g_d[r0];
        const float d1 = g_d[r1];
        #pragma unroll
        for (int nt = 0; nt < 4; nt++) {
            const int col = nBase + wn * 32 + nt * 8 + tig * 2;
            const float2 bv = *reinterpret_cast<const float2*>(bias + col);
            const float2 s0 = *reinterpret_cast<const float2*>(g_supp + (size_t)r0 * FEAT + col);
            const float2 s1 = *reinterpret_cast<const float2*>(g_supp + (size_t)r1 * FEAT + col);
            float2 o0, o1;
            o0.x = fmaf(d0, acc[mt][nt][0] + d0 * s0.x, bv.x);
            o0.y = fmaf(d0, acc[mt][nt][1] + d0 * s0.y, bv.y);
            o1.x = fmaf(d1, acc[mt][nt][2] + d1 * s1.x, bv.x);
            o1.y = fmaf(d1, acc[mt][nt][3] + d1 * s1.y, bv.y);
            *reinterpret_cast<float2*>(out + (size_t)r0 * FEAT + col) = o0;
            *reinterpret_cast<float2*>(out + (size_t)r1 * FEAT + col) = o1;
        }
    }
}

// ---------------------------------------------------------------------------
extern "C" void kernel_launch(void* const* d_in, const int* in_sizes, int n_in,
                              void* d_out, int out_size) {
    const float* input  = (const float*)d_in[0];   // [8192, 256]
    const float* adj    = (const float*)d_in[1];   // [8192, 8192]
    const float* weight = (const float*)d_in[2];   // [256, 256]
    const float* bias   = (const float*)d_in[3];   // [256]
    float* out = (float*)d_out;

    cudaFuncSetAttribute(gcn_main_gemm, cudaFuncAttributeMaxDynamicSharedMemorySize, MAIN_SMEM);

    prep_fused_kernel<<<GEMM_BLOCKS + N_NODES, 256>>>(adj, input, weight);
    {
        dim3 grid(FEAT / 128, N_NODES / 128);   // (2, 64)
        gcn_main_gemm<<<grid, 256, MAIN_SMEM>>>(adj, out, bias);
    }
}

// round 9
// speedup vs baseline: 1.4017x; 1.1411x over previous
#include <cuda_runtime.h>
#include <cstdint>

#define N_NODES 8192
#define FEAT    256

// ---------------------------------------------------------------------------
// Device scratch
// ---------------------------------------------------------------------------
__device__ __align__(128) float g_d[N_NODES];            // rsqrt degree
__device__ __align__(128) float g_supp[N_NODES * FEAT];  // raw fp32 (input @ weight)
__device__ __align__(128) float g_part[2 * N_NODES * FEAT];  // split-K partials

// ---------------------------------------------------------------------------
// helpers
// ---------------------------------------------------------------------------
__device__ __forceinline__ uint32_t smem_to_u32(const void* p) {
    uint32_t a;
    asm("{ .reg .u64 t; cvta.to.shared.u64 t, %1; cvt.u32.u64 %0, t; }" : "=r"(a) : "l"(p));
    return a;
}
#define CP_ASYNC_CG(smem, gptr) \
    asm volatile("cp.async.cg.shared.global [%0], [%1], 16;" :: "r"((uint32_t)(smem)), "l"(gptr) : "memory")
#define CP_COMMIT() asm volatile("cp.async.commit_group;" ::: "memory")
#define CP_WAIT2()  asm volatile("cp.async.wait_group 2;" ::: "memory")

__device__ __forceinline__ void mma_tf32(float* c, const uint32_t* a, const uint32_t* b) {
    asm volatile(
        "mma.sync.aligned.m16n8k8.row.col.f32.tf32.tf32.f32 "
        "{%0,%1,%2,%3}, {%4,%5,%6,%7}, {%8,%9}, {%0,%1,%2,%3};"
        : "+f"(c[0]), "+f"(c[1]), "+f"(c[2]), "+f"(c[3])
        : "r"(a[0]), "r"(a[1]), "r"(a[2]), "r"(a[3]), "r"(b[0]), "r"(b[1]));
}

// ---------------------------------------------------------------------------
// Fused kernel 1 (measured ~75us):
//   blocks [0, 128)      : supp0 = input @ weight
//   blocks [128, 8320)   : d[row] = rsqrt(1 + rowsum(adj))
// ---------------------------------------------------------------------------
#define BM 128
#define BN 128
#define BK 16
#define TM 8
#define TN 8
#define GEMM_BLOCKS ((N_NODES / BM) * (FEAT / BN))   // 128

__global__ __launch_bounds__(256, 2)
void prep_fused_kernel(const float* __restrict__ adj,
                       const float* __restrict__ input,
                       const float* __restrict__ weight) {
    __shared__ float sh[2 * BK * 128];    // 16KB: As | Bs
    const int tid = threadIdx.x;

    if (blockIdx.x >= GEMM_BLOCKS) {
        // ---- rowsum path ----
        const int row = blockIdx.x - GEMM_BLOCKS;
        const float4* rp = reinterpret_cast<const float4*>(adj + (size_t)row * N_NODES);
        float s = 0.0f;
        #pragma unroll 4
        for (int i = tid; i < N_NODES / 4; i += 256) {
            float4 v = __ldg(rp + i);
            s += (v.x + v.y) + (v.z + v.w);
        }
        #pragma unroll
        for (int o = 16; o > 0; o >>= 1) s += __shfl_down_sync(0xffffffffu, s, o);
        const int lane = tid & 31;
        const int w = tid >> 5;
        if (lane == 0) sh[w] = s;
        __syncthreads();
        if (w == 0) {
            s = (lane < 8) ? sh[lane] : 0.0f;
            #pragma unroll
            for (int o = 4; o > 0; o >>= 1) s += __shfl_down_sync(0xffffffffu, s, o);
            if (lane == 0) g_d[row] = rsqrtf(s + 1.0f);
        }
        return;
    }

    // ---- small GEMM path: supp0 = input @ weight ----
    float (*As)[BM] = reinterpret_cast<float (*)[BM]>(sh);
    float (*Bs)[BN] = reinterpret_cast<float (*)[BN]>(sh + BK * BM);
    const int rowBase = (blockIdx.x >> 1) * BM;
    const int colBase = (blockIdx.x & 1) * BN;
    const int ty = tid >> 4, tx = tid & 15;
    const int aRow = tid >> 2, aCol = (tid & 3) << 2;
    const int bRow = tid >> 5, bCol = (tid & 31) << 2;
    const int K = FEAT;

    float acc[TM][TN];
    #pragma unroll
    for (int m = 0; m < TM; m++)
        #pragma unroll
        for (int n = 0; n < TN; n++) acc[m][n] = 0.0f;

    for (int k0 = 0; k0 < K; k0 += BK) {
        #pragma unroll
        for (int r = 0; r < BM; r += 64) {
            float4 v = *reinterpret_cast<const float4*>(input + (size_t)(rowBase + aRow + r) * K + (k0 + aCol));
            As[aCol + 0][aRow + r] = v.x; As[aCol + 1][aRow + r] = v.y;
            As[aCol + 2][aRow + r] = v.z; As[aCol + 3][aRow + r] = v.w;
        }
        #pragma unroll
        for (int r = 0; r < BK; r += 8)
            *reinterpret_cast<float4*>(&Bs[bRow + r][bCol]) =
                *reinterpret_cast<const float4*>(weight + (size_t)(k0 + bRow + r) * FEAT + (colBase + bCol));
        __syncthreads();
        #pragma unroll
        for (int k = 0; k < BK; k++) {
            float a[TM], b[TN];
            *reinterpret_cast<float4*>(&a[0]) = *reinterpret_cast<const float4*>(&As[k][ty * TM]);
            *reinterpret_cast<float4*>(&a[4]) = *reinterpret_cast<const float4*>(&As[k][ty * TM + 4]);
            *reinterpret_cast<float4*>(&b[0]) = *reinterpret_cast<const float4*>(&Bs[k][tx * TN]);
            *reinterpret_cast<float4*>(&b[4]) = *reinterpret_cast<const float4*>(&Bs[k][tx * TN + 4]);
            #pragma unroll
            for (int m = 0; m < TM; m++)
                #pragma unroll
                for (int n = 0; n < TN; n++) acc[m][n] = fmaf(a[m], b[n], acc[m][n]);
        }
        __syncthreads();
    }
    #pragma unroll
    for (int m = 0; m < TM; m++) {
        const int gr = rowBase + ty * TM + m;
        #pragma unroll
        for (int n4 = 0; n4 < TN; n4 += 4) {
            const int gc = colBase + tx * TN + n4;
            float4 o;
            o.x = acc[m][n4 + 0]; o.y = acc[m][n4 + 1];
            o.z = acc[m][n4 + 2]; o.w = acc[m][n4 + 3];
            *reinterpret_cast<float4*>(g_supp + (size_t)gr * FEAT + gc) = o;
        }
    }
}

// ---------------------------------------------------------------------------
// Kernel 2: partial[split] = adj[:, kr] @ (d_k * supp0[kr, :])
// TF32 mma.sync m16n8k8, CTA 128x256 (FULL N), 8 warps (warp tile 64x64),
// split-K=2 (grid 128), K-step 32, 4-stage cp.async pipeline,
// raw-bit tf32 operands. Crossbar bytes/MMA: 141 vs 280 in old shape.
// ---------------------------------------------------------------------------
#define SA 36                                  // A smem row stride (floats)
#define SB 264                                 // B smem row stride (floats)
#define D_OFF (128 * SA + 32 * SB)             // 13056
#define STAGE_FLOATS (D_OFF + 32)              // 13088
#define STAGE_BYTES  (STAGE_FLOATS * 4)        // 52352
#define NSTAGES 4
#define PREF 3
#define MAIN_SMEM (NSTAGES * STAGE_BYTES)      // 209408
#define KSPLIT (N_NODES / 2)                   // 4096
#define NITER (KSPLIT / 32)                    // 128

__global__ __launch_bounds__(256, 1)
void gcn_main_gemm(const float* __restrict__ adj) {
    extern __shared__ float smem[];
    const uint32_t sb_u32 = smem_to_u32(smem);

    const int tid = threadIdx.x;
    const int wid = tid >> 5;
    const int lane = tid & 31;
    const int gid = lane >> 2;      // 0..7
    const int tig = lane & 3;       // 0..3
    const int wm = wid >> 2;        // 0..1  (64-row band)
    const int wn = wid & 3;         // 0..3  (64-col band of 256)

    const int mBase = blockIdx.y * 128;
    const int split = blockIdx.x;   // 0..1

    const float* Abase = adj + (size_t)mBase * N_NODES + (size_t)split * KSPLIT;
    const float* Bbase = g_supp + (size_t)(split * KSPLIT) * FEAT;
    const float* Dbase = g_d + split * KSPLIT;

    float acc[4][8][4];
    #pragma unroll
    for (int mt = 0; mt < 4; mt++)
        #pragma unroll
        for (int nt = 0; nt < 8; nt++)
            #pragma unroll
            for (int c = 0; c < 4; c++) acc[mt][nt][c] = 0.0f;

    auto load_stage = [&](int s) {
        const int slot = s & (NSTAGES - 1);
        const uint32_t a_s = sb_u32 + slot * STAGE_BYTES;
        const uint32_t b_s = a_s + 128 * SA * 4;
        const uint32_t d_s = a_s + D_OFF * 4;
        const float* ag = Abase + s * 32;
        const float* bg = Bbase + (size_t)(s * 32) * FEAT;
        #pragma unroll
        for (int i = 0; i < 4; i++) {            // A: 128r x 32k = 1024 granules
            const int g = tid + i * 256;
            const int r = g >> 3, q = g & 7;
            CP_ASYNC_CG(a_s + (r * SA + q * 4) * 4, ag + (size_t)r * N_NODES + q * 4);
        }
        #pragma unroll
        for (int i = 0; i < 8; i++) {            // B: 32k x 256n = 2048 granules
            const int g = tid + i * 256;
            const int k = g >> 6, q = g & 63;
            CP_ASYNC_CG(b_s + (k * SB + q * 4) * 4, bg + (size_t)k * FEAT + q * 4);
        }
        if (tid < 8) {                           // D: 32 floats
            CP_ASYNC_CG(d_s + tid * 16, Dbase + s * 32 + tid * 4);
        }
    };

    #pragma unroll
    for (int p = 0; p < PREF; p++) { load_stage(p); CP_COMMIT(); }

    for (int s = 0; s < NITER; s++) {
        CP_WAIT2();
        __syncthreads();     // all warps done with stage s-1 -> slot reusable

        if (s + PREF < NITER) { load_stage(s + PREF); }
        CP_COMMIT();

        const int slot = s & (NSTAGES - 1);
        const float* As = smem + slot * STAGE_FLOATS;
        const float* Bs = As + 128 * SA;
        const float* Ds = As + D_OFF;

        #pragma unroll
        for (int k8 = 0; k8 < 4; k8++) {
            const int kk = k8 * 8;
            const float d0 = Ds[kk + tig];
            const float d1 = Ds[kk + tig + 4];
            uint32_t a[4][4], b[8][2];
            #pragma unroll
            for (int mt = 0; mt < 4; mt++) {
                const int r = wm * 64 + mt * 16 + gid;
                a[mt][0] = __float_as_uint(As[r * SA + kk + tig]);
                a[mt][1] = __float_as_uint(As[(r + 8) * SA + kk + tig]);
                a[mt][2] = __float_as_uint(As[r * SA + kk + tig + 4]);
                a[mt][3] = __float_as_uint(As[(r + 8) * SA + kk + tig + 4]);
            }
            #pragma unroll
            for (int nt = 0; nt < 8; nt++) {
                const int n = wn * 64 + nt * 8 + gid;
                b[nt][0] = __float_as_uint(Bs[(kk + tig) * SB + n] * d0);
                b[nt][1] = __float_as_uint(Bs[(kk + tig + 4) * SB + n] * d1);
            }
            #pragma unroll
            for (int mt = 0; mt < 4; mt++)
                #pragma unroll
                for (int nt = 0; nt < 8; nt++)
                    mma_tf32(acc[mt][nt], a[mt], b[nt]);
        }
        __syncthreads();
    }

    // write raw partials
    float* dst = g_part + (size_t)split * N_NODES * FEAT;
    #pragma unroll
    for (int mt = 0; mt < 4; mt++) {
        const int r0 = mBase + wm * 64 + mt * 16 + gid;
        const int r1 = r0 + 8;
        #pragma unroll
        for (int nt = 0; nt < 8; nt++) {
            const int col = wn * 64 + nt * 8 + tig * 2;
            float2 o0, o1;
            o0.x = acc[mt][nt][0]; o0.y = acc[mt][nt][1];
            o1.x = acc[mt][nt][2]; o1.y = acc[mt][nt][3];
            *reinterpret_cast<float2*>(dst + (size_t)r0 * FEAT + col) = o0;
            *reinterpret_cast<float2*>(dst + (size_t)r1 * FEAT + col) = o1;
        }
    }
}

// ---------------------------------------------------------------------------
// Kernel 3: fixup  out = d_i*(p0 + p1) + d_i^2 * supp0[i,:] + bias
// ---------------------------------------------------------------------------
__global__ __launch_bounds__(256)
void fixup_kernel(float* __restrict__ out, const float* __restrict__ bias) {
    const size_t i = (size_t)blockIdx.x * 256 + threadIdx.x;  // over 2M float4
    const size_t row = i >> 6;
    const int c4 = (int)(i & 63);
    const float d = g_d[row];
    const float4 p0 = *reinterpret_cast<const float4*>(g_part + row * FEAT + c4 * 4);
    const float4 p1 = *reinterpret_cast<const float4*>(g_part + (size_t)N_NODES * FEAT + row * FEAT + c4 * 4);
    const float4 sv = *reinterpret_cast<const float4*>(g_supp + row * FEAT + c4 * 4);
    const float4 bv = *reinterpret_cast<const float4*>(bias + c4 * 4);
    float4 o;
    o.x = fmaf(d, p0.x + p1.x + d * sv.x, bv.x);
    o.y = fmaf(d, p0.y + p1.y + d * sv.y, bv.y);
    o.z = fmaf(d, p0.z + p1.z + d * sv.z, bv.z);
    o.w = fmaf(d, p0.w + p1.w + d * sv.w, bv.w);
    *reinterpret_cast<float4*>(out + row * FEAT + c4 * 4) = o;
}

// ---------------------------------------------------------------------------
extern "C" void kernel_launch(void* const* d_in, const int* in_sizes, int n_in,
                              void* d_out, int out_size) {
    const float* input  = (const float*)d_in[0];   // [8192, 256]
    const float* adj    = (const float*)d_in[1];   // [8192, 8192]
    const float* weight = (const float*)d_in[2];   // [256, 256]
    const float* bias   = (const float*)d_in[3];   // [256]
    float* out = (float*)d_out;

    cudaFuncSetAttribute(gcn_main_gemm, cudaFuncAttributeMaxDynamicSharedMemorySize, MAIN_SMEM);

    prep_fused_kernel<<<GEMM_BLOCKS + N_NODES, 256>>>(adj, input, weight);
    {
        dim3 grid(2, N_NODES / 128);   // (split, mtile) = 128 CTAs
        gcn_main_gemm<<<grid, 256, MAIN_SMEM>>>(adj);
    }
    fixup_kernel<<<(N_NODES * FEAT / 4) / 256, 256>>>(out, bias);
}

// round 10
// speedup vs baseline: 1.4304x; 1.0205x over previous
#include <cuda_runtime.h>
#include <cstdint>

#define N_NODES 8192
#define FEAT    256

// ---------------------------------------------------------------------------
// Device scratch
// ---------------------------------------------------------------------------
__device__ __align__(128) float g_d[N_NODES];            // rsqrt degree
__device__ __align__(128) float g_supp[N_NODES * FEAT];  // (input@weight), then d_k-scaled
__device__ __align__(128) float g_part[2 * N_NODES * FEAT];  // split-K partials

// ---------------------------------------------------------------------------
// helpers
// ---------------------------------------------------------------------------
__device__ __forceinline__ uint32_t smem_to_u32(const void* p) {
    uint32_t a;
    asm("{ .reg .u64 t; cvta.to.shared.u64 t, %1; cvt.u32.u64 %0, t; }" : "=r"(a) : "l"(p));
    return a;
}
#define CP_ASYNC_CG(smem, gptr) \
    asm volatile("cp.async.cg.shared.global [%0], [%1], 16;" :: "r"((uint32_t)(smem)), "l"(gptr) : "memory")
#define CP_COMMIT() asm volatile("cp.async.commit_group;" ::: "memory")
#define CP_WAIT2()  asm volatile("cp.async.wait_group 2;" ::: "memory")

__device__ __forceinline__ void mma_tf32(float* c, const uint32_t* a, const uint32_t* b) {
    asm volatile(
        "mma.sync.aligned.m16n8k8.row.col.f32.tf32.tf32.f32 "
        "{%0,%1,%2,%3}, {%4,%5,%6,%7}, {%8,%9}, {%0,%1,%2,%3};"
        : "+f"(c[0]), "+f"(c[1]), "+f"(c[2]), "+f"(c[3])
        : "r"(a[0]), "r"(a[1]), "r"(a[2]), "r"(a[3]), "r"(b[0]), "r"(b[1]));
}

// ---------------------------------------------------------------------------
// Fused kernel 1 (measured ~75us):
//   blocks [0, 128)      : supp0 = input @ weight
//   blocks [128, 8320)   : d[row] = rsqrt(1 + rowsum(adj))
// ---------------------------------------------------------------------------
#define BM 128
#define BN 128
#define BK 16
#define TM 8
#define TN 8
#define GEMM_BLOCKS ((N_NODES / BM) * (FEAT / BN))   // 128

__global__ __launch_bounds__(256, 2)
void prep_fused_kernel(const float* __restrict__ adj,
                       const float* __restrict__ input,
                       const float* __restrict__ weight) {
    __shared__ float sh[2 * BK * 128];    // 16KB: As | Bs
    const int tid = threadIdx.x;

    if (blockIdx.x >= GEMM_BLOCKS) {
        // ---- rowsum path ----
        const int row = blockIdx.x - GEMM_BLOCKS;
        const float4* rp = reinterpret_cast<const float4*>(adj + (size_t)row * N_NODES);
        float s = 0.0f;
        #pragma unroll 4
        for (int i = tid; i < N_NODES / 4; i += 256) {
            float4 v = __ldg(rp + i);
            s += (v.x + v.y) + (v.z + v.w);
        }
        #pragma unroll
        for (int o = 16; o > 0; o >>= 1) s += __shfl_down_sync(0xffffffffu, s, o);
        const int lane = tid & 31;
        const int w = tid >> 5;
        if (lane == 0) sh[w] = s;
        __syncthreads();
        if (w == 0) {
            s = (lane < 8) ? sh[lane] : 0.0f;
            #pragma unroll
            for (int o = 4; o > 0; o >>= 1) s += __shfl_down_sync(0xffffffffu, s, o);
            if (lane == 0) g_d[row] = rsqrtf(s + 1.0f);
        }
        return;
    }

    // ---- small GEMM path: supp0 = input @ weight ----
    float (*As)[BM] = reinterpret_cast<float (*)[BM]>(sh);
    float (*Bs)[BN] = reinterpret_cast<float (*)[BN]>(sh + BK * BM);
    const int rowBase = (blockIdx.x >> 1) * BM;
    const int colBase = (blockIdx.x & 1) * BN;
    const int ty = tid >> 4, tx = tid & 15;
    const int aRow = tid >> 2, aCol = (tid & 3) << 2;
    const int bRow = tid >> 5, bCol = (tid & 31) << 2;
    const int K = FEAT;

    float acc[TM][TN];
    #pragma unroll
    for (int m = 0; m < TM; m++)
        #pragma unroll
        for (int n = 0; n < TN; n++) acc[m][n] = 0.0f;

    for (int k0 = 0; k0 < K; k0 += BK) {
        #pragma unroll
        for (int r = 0; r < BM; r += 64) {
            float4 v = *reinterpret_cast<const float4*>(input + (size_t)(rowBase + aRow + r) * K + (k0 + aCol));
            As[aCol + 0][aRow + r] = v.x; As[aCol + 1][aRow + r] = v.y;
            As[aCol + 2][aRow + r] = v.z; As[aCol + 3][aRow + r] = v.w;
        }
        #pragma unroll
        for (int r = 0; r < BK; r += 8)
            *reinterpret_cast<float4*>(&Bs[bRow + r][bCol]) =
                *reinterpret_cast<const float4*>(weight + (size_t)(k0 + bRow + r) * FEAT + (colBase + bCol));
        __syncthreads();
        #pragma unroll
        for (int k = 0; k < BK; k++) {
            float a[TM], b[TN];
            *reinterpret_cast<float4*>(&a[0]) = *reinterpret_cast<const float4*>(&As[k][ty * TM]);
            *reinterpret_cast<float4*>(&a[4]) = *reinterpret_cast<const float4*>(&As[k][ty * TM + 4]);
            *reinterpret_cast<float4*>(&b[0]) = *reinterpret_cast<const float4*>(&Bs[k][tx * TN]);
            *reinterpret_cast<float4*>(&b[4]) = *reinterpret_cast<const float4*>(&Bs[k][tx * TN + 4]);
            #pragma unroll
            for (int m = 0; m < TM; m++)
                #pragma unroll
                for (int n = 0; n < TN; n++) acc[m][n] = fmaf(a[m], b[n], acc[m][n]);
        }
        __syncthreads();
    }
    #pragma unroll
    for (int m = 0; m < TM; m++) {
        const int gr = rowBase + ty * TM + m;
        #pragma unroll
        for (int n4 = 0; n4 < TN; n4 += 4) {
            const int gc = colBase + tx * TN + n4;
            float4 o;
            o.x = acc[m][n4 + 0]; o.y = acc[m][n4 + 1];
            o.z = acc[m][n4 + 2]; o.w = acc[m][n4 + 3];
            *reinterpret_cast<float4*>(g_supp + (size_t)gr * FEAT + gc) = o;
        }
    }
}

// ---------------------------------------------------------------------------
// Kernel 2: g_supp[k,:] *= d_k   (in-place, ~3us)
// ---------------------------------------------------------------------------
__global__ __launch_bounds__(256)
void scale_supp_kernel() {
    const size_t i = (size_t)blockIdx.x * 256 + threadIdx.x;  // over 512K float4
    const size_t row = i >> 6;
    const int c4 = (int)(i & 63);
    const float d = g_d[row];
    float4* p = reinterpret_cast<float4*>(g_supp + row * FEAT + c4 * 4);
    float4 v = *p;
    v.x *= d; v.y *= d; v.z *= d; v.w *= d;
    *p = v;
}

// ---------------------------------------------------------------------------
// Kernel 3: partial[split] = adj[:, kr] @ suppd[kr, :]   (suppd = d_k*supp0)
// TF32 mma.sync m16n8k8, CTA 128x256 (FULL N), 8 warps (warp tile 64x64),
// split-K=2 (grid 128), K-step 32, 4-stage cp.async pipeline,
// single barrier per stage, pure LDS+HMMA inner loop, raw-bit tf32.
// ---------------------------------------------------------------------------
#define SA 36                                  // A smem row stride (floats)
#define SB 264                                 // B smem row stride (floats)
#define STAGE_FLOATS (128 * SA + 32 * SB)      // 13056
#define STAGE_BYTES  (STAGE_FLOATS * 4)        // 52224
#define NSTAGES 4
#define PREF 3
#define MAIN_SMEM (NSTAGES * STAGE_BYTES)      // 208896
#define KSPLIT (N_NODES / 2)                   // 4096
#define NITER (KSPLIT / 32)                    // 128

__global__ __launch_bounds__(256, 1)
void gcn_main_gemm(const float* __restrict__ adj) {
    extern __shared__ float smem[];
    const uint32_t sb_u32 = smem_to_u32(smem);

    const int tid = threadIdx.x;
    const int wid = tid >> 5;
    const int lane = tid & 31;
    const int gid = lane >> 2;      // 0..7
    const int tig = lane & 3;       // 0..3
    const int wm = wid >> 2;        // 0..1  (64-row band)
    const int wn = wid & 3;         // 0..3  (64-col band of 256)

    const int mBase = blockIdx.y * 128;
    const int split = blockIdx.x;   // 0..1

    const float* Abase = adj + (size_t)mBase * N_NODES + (size_t)split * KSPLIT;
    const float* Bbase = g_supp + (size_t)(split * KSPLIT) * FEAT;

    float acc[4][8][4];
    #pragma unroll
    for (int mt = 0; mt < 4; mt++)
        #pragma unroll
        for (int nt = 0; nt < 8; nt++)
            #pragma unroll
            for (int c = 0; c < 4; c++) acc[mt][nt][c] = 0.0f;

    auto load_stage = [&](int s) {
        const int slot = s & (NSTAGES - 1);
        const uint32_t a_s = sb_u32 + slot * STAGE_BYTES;
        const uint32_t b_s = a_s + 128 * SA * 4;
        const float* ag = Abase + s * 32;
        const float* bg = Bbase + (size_t)(s * 32) * FEAT;
        #pragma unroll
        for (int i = 0; i < 4; i++) {            // A: 128r x 32k = 1024 granules
            const int g = tid + i * 256;
            const int r = g >> 3, q = g & 7;
            CP_ASYNC_CG(a_s + (r * SA + q * 4) * 4, ag + (size_t)r * N_NODES + q * 4);
        }
        #pragma unroll
        for (int i = 0; i < 8; i++) {            // B: 32k x 256n = 2048 granules
            const int g = tid + i * 256;
            const int k = g >> 6, q = g & 63;
            CP_ASYNC_CG(b_s + (k * SB + q * 4) * 4, bg + (size_t)k * FEAT + q * 4);
        }
    };

    #pragma unroll
    for (int p = 0; p < PREF; p++) { load_stage(p); CP_COMMIT(); }

    for (int s = 0; s < NITER; s++) {
        CP_WAIT2();
        __syncthreads();     // stage s data visible; stage s-1 consumed by all

        if (s + PREF < NITER) { load_stage(s + PREF); }
        CP_COMMIT();

        const int slot = s & (NSTAGES - 1);
        const float* As = smem + slot * STAGE_FLOATS;
        const float* Bs = As + 128 * SA;

        #pragma unroll
        for (int k8 = 0; k8 < 4; k8++) {
            const int kk = k8 * 8;
            uint32_t a[4][4], b[8][2];
            #pragma unroll
            for (int mt = 0; mt < 4; mt++) {
                const int r = wm * 64 + mt * 16 + gid;
                a[mt][0] = __float_as_uint(As[r * SA + kk + tig]);
                a[mt][1] = __float_as_uint(As[(r + 8) * SA + kk + tig]);
                a[mt][2] = __float_as_uint(As[r * SA + kk + tig + 4]);
                a[mt][3] = __float_as_uint(As[(r + 8) * SA + kk + tig + 4]);
            }
            #pragma unroll
            for (int nt = 0; nt < 8; nt++) {
                const int n = wn * 64 + nt * 8 + gid;
                b[nt][0] = __float_as_uint(Bs[(kk + tig) * SB + n]);
                b[nt][1] = __float_as_uint(Bs[(kk + tig + 4) * SB + n]);
            }
            #pragma unroll
            for (int mt = 0; mt < 4; mt++)
                #pragma unroll
                for (int nt = 0; nt < 8; nt++)
                    mma_tf32(acc[mt][nt], a[mt], b[nt]);
        }
    }

    // write raw partials
    float* dst = g_part + (size_t)split * N_NODES * FEAT;
    #pragma unroll
    for (int mt = 0; mt < 4; mt++) {
        const int r0 = mBase + wm * 64 + mt * 16 + gid;
        const int r1 = r0 + 8;
        #pragma unroll
        for (int nt = 0; nt < 8; nt++) {
            const int col = wn * 64 + nt * 8 + tig * 2;
            float2 o0, o1;
            o0.x = acc[mt][nt][0]; o0.y = acc[mt][nt][1];
            o1.x = acc[mt][nt][2]; o1.y = acc[mt][nt][3];
            *reinterpret_cast<float2*>(dst + (size_t)r0 * FEAT + col) = o0;
            *reinterpret_cast<float2*>(dst + (size_t)r1 * FEAT + col) = o1;
        }
    }
}

// ---------------------------------------------------------------------------
// Kernel 4: fixup  out = d_i*(p0 + p1 + suppd[i,:]) + bias
//   (d_i^2 * supp0[i,:] == d_i * suppd[i,:] since suppd = d*supp0)
// ---------------------------------------------------------------------------
__global__ __launch_bounds__(256)
void fixup_kernel(float* __restrict__ out, const float* __restrict__ bias) {
    const size_t i = (size_t)blockIdx.x * 256 + threadIdx.x;  // over 2M float4
    const size_t row = i >> 6;
    const int c4 = (int)(i & 63);
    const float d = g_d[row];
    const float4 p0 = *reinterpret_cast<const float4*>(g_part + row * FEAT + c4 * 4);
    const float4 p1 = *reinterpret_cast<const float4*>(g_part + (size_t)N_NODES * FEAT + row * FEAT + c4 * 4);
    const float4 sv = *reinterpret_cast<const float4*>(g_supp + row * FEAT + c4 * 4);
    const float4 bv = *reinterpret_cast<const float4*>(bias + c4 * 4);
    float4 o;
    o.x = fmaf(d, p0.x + p1.x + sv.x, bv.x);
    o.y = fmaf(d, p0.y + p1.y + sv.y, bv.y);
    o.z = fmaf(d, p0.z + p1.z + sv.z, bv.z);
    o.w = fmaf(d, p0.w + p1.w + sv.w, bv.w);
    *reinterpret_cast<float4*>(out + row * FEAT + c4 * 4) = o;
}

// ---------------------------------------------------------------------------
extern "C" void kernel_launch(void* const* d_in, const int* in_sizes, int n_in,
                              void* d_out, int out_size) {
    const float* input  = (const float*)d_in[0];   // [8192, 256]
    const float* adj    = (const float*)d_in[1];   // [8192, 8192]
    const float* weight = (const float*)d_in[2];   // [256, 256]
    const float* bias   = (const float*)d_in[3];   // [256]
    float* out = (float*)d_out;

    cudaFuncSetAttribute(gcn_main_gemm, cudaFuncAttributeMaxDynamicSharedMemorySize, MAIN_SMEM);

    prep_fused_kernel<<<GEMM_BLOCKS + N_NODES, 256>>>(adj, input, weight);
    scale_supp_kernel<<<(N_NODES * FEAT / 4) / 256, 256>>>();
    {
        dim3 grid(2, N_NODES / 128);   // (split, mtile) = 128 CTAs
        gcn_main_gemm<<<grid, 256, MAIN_SMEM>>>(adj);
    }
    fixup_kernel<<<(N_NODES * FEAT / 4) / 256, 256>>>(out, bias);
}

// round 11
// speedup vs baseline: 1.4503x; 1.0140x over previous
#include <cuda_runtime.h>
#include <cstdint>

#define N_NODES 8192
#define FEAT    256

// ---------------------------------------------------------------------------
// Device scratch
// ---------------------------------------------------------------------------
__device__ __align__(128) float g_d[N_NODES];            // rsqrt degree
__device__ __align__(128) float g_supp[N_NODES * FEAT];  // d_k * (input @ weight)
__device__ __align__(128) float g_part[2 * N_NODES * FEAT];  // split-K partials

// ---------------------------------------------------------------------------
// helpers
// ---------------------------------------------------------------------------
__device__ __forceinline__ uint32_t smem_to_u32(const void* p) {
    uint32_t a;
    asm("{ .reg .u64 t; cvta.to.shared.u64 t, %1; cvt.u32.u64 %0, t; }" : "=r"(a) : "l"(p));
    return a;
}
#define CP_ASYNC_CG(smem, gptr) \
    asm volatile("cp.async.cg.shared.global [%0], [%1], 16;" :: "r"((uint32_t)(smem)), "l"(gptr) : "memory")
#define CP_COMMIT() asm volatile("cp.async.commit_group;" ::: "memory")
#define CP_WAIT0()  asm volatile("cp.async.wait_group 0;" ::: "memory")

__device__ __forceinline__ void mma_tf32(float* c, const uint32_t* a, const uint32_t* b) {
    asm volatile(
        "mma.sync.aligned.m16n8k8.row.col.f32.tf32.tf32.f32 "
        "{%0,%1,%2,%3}, {%4,%5,%6,%7}, {%8,%9}, {%0,%1,%2,%3};"
        : "+f"(c[0]), "+f"(c[1]), "+f"(c[2]), "+f"(c[3])
        : "r"(a[0]), "r"(a[1]), "r"(a[2]), "r"(a[3]), "r"(b[0]), "r"(b[1]));
}

// ---------------------------------------------------------------------------
// Kernel 1: d[i] = rsqrt(1 + rowsum(adj))   (R1 version: 43us, occ 95%)
// ---------------------------------------------------------------------------
__global__ __launch_bounds__(256)
void rowsum_rsqrt_kernel(const float* __restrict__ adj) {
    const int row = blockIdx.x;
    const float4* rp = reinterpret_cast<const float4*>(adj + (size_t)row * N_NODES);
    float s = 0.0f;
    #pragma unroll 4
    for (int i = threadIdx.x; i < N_NODES / 4; i += blockDim.x) {
        float4 v = __ldg(rp + i);
        s += (v.x + v.y) + (v.z + v.w);
    }
    #pragma unroll
    for (int o = 16; o > 0; o >>= 1) s += __shfl_down_sync(0xffffffffu, s, o);
    __shared__ float red[8];
    const int lane = threadIdx.x & 31;
    const int w = threadIdx.x >> 5;
    if (lane == 0) red[w] = s;
    __syncthreads();
    if (w == 0) {
        s = (lane < 8) ? red[lane] : 0.0f;
        #pragma unroll
        for (int o = 4; o > 0; o >>= 1) s += __shfl_down_sync(0xffffffffu, s, o);
        if (lane == 0) g_d[row] = rsqrtf(s + 1.0f);
    }
}

// ---------------------------------------------------------------------------
// Kernel 2: g_supp = d[k] * (input @ weight)   (d fold in epilogue)
// ---------------------------------------------------------------------------
#define BM 128
#define BN 128
#define BK 16
#define TM 8
#define TN 8

__global__ __launch_bounds__(256, 2)
void small_gemm_kernel(const float* __restrict__ A, const float* __restrict__ B) {
    __shared__ float As[BK][BM];
    __shared__ float Bs[BK][BN];
    const int tid = threadIdx.x;
    const int rowBase = blockIdx.y * BM;
    const int colBase = blockIdx.x * BN;
    const int ty = tid >> 4, tx = tid & 15;
    const int aRow = tid >> 2, aCol = (tid & 3) << 2;
    const int bRow = tid >> 5, bCol = (tid & 31) << 2;
    const int K = FEAT;

    float acc[TM][TN];
    #pragma unroll
    for (int m = 0; m < TM; m++)
        #pragma unroll
        for (int n = 0; n < TN; n++) acc[m][n] = 0.0f;

    for (int k0 = 0; k0 < K; k0 += BK) {
        #pragma unroll
        for (int r = 0; r < BM; r += 64) {
            float4 v = *reinterpret_cast<const float4*>(A + (size_t)(rowBase + aRow + r) * K + (k0 + aCol));
            As[aCol + 0][aRow + r] = v.x; As[aCol + 1][aRow + r] = v.y;
            As[aCol + 2][aRow + r] = v.z; As[aCol + 3][aRow + r] = v.w;
        }
        #pragma unroll
        for (int r = 0; r < BK; r += 8)
            *reinterpret_cast<float4*>(&Bs[bRow + r][bCol]) =
                *reinterpret_cast<const float4*>(B + (size_t)(k0 + bRow + r) * FEAT + (colBase + bCol));
        __syncthreads();
        #pragma unroll
        for (int k = 0; k < BK; k++) {
            float a[TM], b[TN];
            *reinterpret_cast<float4*>(&a[0]) = *reinterpret_cast<const float4*>(&As[k][ty * TM]);
            *reinterpret_cast<float4*>(&a[4]) = *reinterpret_cast<const float4*>(&As[k][ty * TM + 4]);
            *reinterpret_cast<float4*>(&b[0]) = *reinterpret_cast<const float4*>(&Bs[k][tx * TN]);
            *reinterpret_cast<float4*>(&b[4]) = *reinterpret_cast<const float4*>(&Bs[k][tx * TN + 4]);
            #pragma unroll
            for (int m = 0; m < TM; m++)
                #pragma unroll
                for (int n = 0; n < TN; n++) acc[m][n] = fmaf(a[m], b[n], acc[m][n]);
        }
        __syncthreads();
    }
    #pragma unroll
    for (int m = 0; m < TM; m++) {
        const int gr = rowBase + ty * TM + m;
        const float dr = g_d[gr];
        #pragma unroll
        for (int n4 = 0; n4 < TN; n4 += 4) {
            const int gc = colBase + tx * TN + n4;
            float4 o;
            o.x = dr * acc[m][n4 + 0]; o.y = dr * acc[m][n4 + 1];
            o.z = dr * acc[m][n4 + 2]; o.w = dr * acc[m][n4 + 3];
            *reinterpret_cast<float4*>(g_supp + (size_t)gr * FEAT + gc) = o;
        }
    }
}

// ---------------------------------------------------------------------------
// Kernel 3: partial[split] = adj[:, kr] @ suppd[kr, :]
// TF32 mma.sync m16n8k8, CTA 128x256, 8 warps (64x64), split-K=2,
// K-step 64 (8 k8 groups/stage), 2-stage double buffer, one barrier/stage.
// Per-stage fixed overhead amortized over 2048 MMAs instead of 1024.
// ---------------------------------------------------------------------------
#define SA 68                                  // A smem row stride (floats): 68%32=4 -> conflict-free
#define SB 264                                 // B smem row stride (floats)
#define KT 64
#define STAGE_FLOATS (128 * SA + KT * SB)      // 8704 + 16896 = 25600
#define STAGE_BYTES  (STAGE_FLOATS * 4)        // 102400
#define NSTAGES 2
#define MAIN_SMEM (NSTAGES * STAGE_BYTES)      // 204800
#define KSPLIT (N_NODES / 2)                   // 4096
#define NITER (KSPLIT / KT)                    // 64

__global__ __launch_bounds__(256, 1)
void gcn_main_gemm(const float* __restrict__ adj) {
    extern __shared__ float smem[];
    const uint32_t sb_u32 = smem_to_u32(smem);

    const int tid = threadIdx.x;
    const int wid = tid >> 5;
    const int lane = tid & 31;
    const int gid = lane >> 2;      // 0..7
    const int tig = lane & 3;       // 0..3
    const int wm = wid >> 2;        // 0..1  (64-row band)
    const int wn = wid & 3;         // 0..3  (64-col band of 256)

    const int mBase = blockIdx.y * 128;
    const int split = blockIdx.x;   // 0..1

    const float* Abase = adj + (size_t)mBase * N_NODES + (size_t)split * KSPLIT;
    const float* Bbase = g_supp + (size_t)(split * KSPLIT) * FEAT;

    float acc[4][8][4];
    #pragma unroll
    for (int mt = 0; mt < 4; mt++)
        #pragma unroll
        for (int nt = 0; nt < 8; nt++)
            #pragma unroll
            for (int c = 0; c < 4; c++) acc[mt][nt][c] = 0.0f;

    // one stage = A 128x64 + B 64x256
    auto load_stage = [&](int s) {
        const int slot = s & (NSTAGES - 1);
        const uint32_t a_s = sb_u32 + slot * STAGE_BYTES;
        const uint32_t b_s = a_s + 128 * SA * 4;
        const float* ag = Abase + s * KT;
        const float* bg = Bbase + (size_t)(s * KT) * FEAT;
        #pragma unroll
        for (int i = 0; i < 8; i++) {            // A: 128r x 64k = 2048 granules
            const int g = tid + i * 256;
            const int r = g >> 4, q = g & 15;
            CP_ASYNC_CG(a_s + (r * SA + q * 4) * 4, ag + (size_t)r * N_NODES + q * 4);
        }
        #pragma unroll
        for (int i = 0; i < 16; i++) {           // B: 64k x 256n = 4096 granules
            const int g = tid + i * 256;
            const int k = g >> 6, q = g & 63;
            CP_ASYNC_CG(b_s + (k * SB + q * 4) * 4, bg + (size_t)k * FEAT + q * 4);
        }
    };

    load_stage(0); CP_COMMIT();

    for (int s = 0; s < NITER; s++) {
        CP_WAIT0();          // stage s resident (this thread)
        __syncthreads();     // all threads' stage-s data visible; stage s-1 consumed

        if (s + 1 < NITER) { load_stage(s + 1); CP_COMMIT(); }
        // load(s+1) targets slot (s+1)&1 == slot of stage s-1: certified free by
        // the barrier above. DRAM transfer overlaps the compute below.

        const int slot = s & (NSTAGES - 1);
        const float* As = smem + slot * STAGE_FLOATS;
        const float* Bs = As + 128 * SA;

        #pragma unroll
        for (int k8 = 0; k8 < KT / 8; k8++) {
            const int kk = k8 * 8;
            uint32_t a[4][4], b[8][2];
            #pragma unroll
            for (int mt = 0; mt < 4; mt++) {
                const int r = wm * 64 + mt * 16 + gid;
                a[mt][0] = __float_as_uint(As[r * SA + kk + tig]);
                a[mt][1] = __float_as_uint(As[(r + 8) * SA + kk + tig]);
                a[mt][2] = __float_as_uint(As[r * SA + kk + tig + 4]);
                a[mt][3] = __float_as_uint(As[(r + 8) * SA + kk + tig + 4]);
            }
            #pragma unroll
            for (int nt = 0; nt < 8; nt++) {
                const int n = wn * 64 + nt * 8 + gid;
                b[nt][0] = __float_as_uint(Bs[(kk + tig) * SB + n]);
                b[nt][1] = __float_as_uint(Bs[(kk + tig + 4) * SB + n]);
            }
            #pragma unroll
            for (int mt = 0; mt < 4; mt++)
                #pragma unroll
                for (int nt = 0; nt < 8; nt++)
                    mma_tf32(acc[mt][nt], a[mt], b[nt]);
        }
    }

    // write raw partials
    float* dst = g_part + (size_t)split * N_NODES * FEAT;
    #pragma unroll
    for (int mt = 0; mt < 4; mt++) {
        const int r0 = mBase + wm * 64 + mt * 16 + gid;
        const int r1 = r0 + 8;
        #pragma unroll
        for (int nt = 0; nt < 8; nt++) {
            const int col = wn * 64 + nt * 8 + tig * 2;
            float2 o0, o1;
            o0.x = acc[mt][nt][0]; o0.y = acc[mt][nt][1];
            o1.x = acc[mt][nt][2]; o1.y = acc[mt][nt][3];
            *reinterpret_cast<float2*>(dst + (size_t)r0 * FEAT + col) = o0;
            *reinterpret_cast<float2*>(dst + (size_t)r1 * FEAT + col) = o1;
        }
    }
}

// ---------------------------------------------------------------------------
// Kernel 4: fixup  out = d_i*(p0 + p1 + suppd[i,:]) + bias
// ---------------------------------------------------------------------------
__global__ __launch_bounds__(256)
void fixup_kernel(float* __restrict__ out, const float* __restrict__ bias) {
    const size_t i = (size_t)blockIdx.x * 256 + threadIdx.x;  // over 2M float4
    const size_t row = i >> 6;
    const int c4 = (int)(i & 63);
    const float d = g_d[row];
    const float4 p0 = *reinterpret_cast<const float4*>(g_part + row * FEAT + c4 * 4);
    const float4 p1 = *reinterpret_cast<const float4*>(g_part + (size_t)N_NODES * FEAT + row * FEAT + c4 * 4);
    const float4 sv = *reinterpret_cast<const float4*>(g_supp + row * FEAT + c4 * 4);
    const float4 bv = *reinterpret_cast<const float4*>(bias + c4 * 4);
    float4 o;
    o.x = fmaf(d, p0.x + p1.x + sv.x, bv.x);
    o.y = fmaf(d, p0.y + p1.y + sv.y, bv.y);
    o.z = fmaf(d, p0.z + p1.z + sv.z, bv.z);
    o.w = fmaf(d, p0.w + p1.w + sv.w, bv.w);
    *reinterpret_cast<float4*>(out + row * FEAT + c4 * 4) = o;
}

// ---------------------------------------------------------------------------
extern "C" void kernel_launch(void* const* d_in, const int* in_sizes, int n_in,
                              void* d_out, int out_size) {
    const float* input  = (const float*)d_in[0];   // [8192, 256]
    const float* adj    = (const float*)d_in[1];   // [8192, 8192]
    const float* weight = (const float*)d_in[2];   // [256, 256]
    const float* bias   = (const float*)d_in[3];   // [256]
    float* out = (float*)d_out;

    cudaFuncSetAttribute(gcn_main_gemm, cudaFuncAttributeMaxDynamicSharedMemorySize, MAIN_SMEM);

    rowsum_rsqrt_kernel<<<N_NODES, 256>>>(adj);
    {
        dim3 grid(FEAT / BN, N_NODES / BM);
        small_gemm_kernel<<<grid, 256>>>(input, weight);
    }
    {
        dim3 grid(2, N_NODES / 128);   // (split, mtile) = 128 CTAs
        gcn_main_gemm<<<grid, 256, MAIN_SMEM>>>(adj);
    }
    fixup_kernel<<<(N_NODES * FEAT / 4) / 256, 256>>>(out, bias);
}